// round 8
// baseline (speedup 1.0000x reference)
#include <cuda_runtime.h>

// TemporalAttention: B=2, M=16, C=256, H=W=64 (HW=4096), T=1024
// out[b,o,p] = sum_c Wv[o,c] * ( sum_m softmax_m(scale * qk[b]·x[b,m,:,p]) * x[b,m,c,p] ) + bv[o]
// qk[b] = scale * Wk^T (Wq t[b] + bq); bk cancels in softmax; bv hoists (sum_m p_m = 1).

#define BDIM 512
#define NWARP 16
#define CC   256
#define HWP  4096
#define MMAPS 16
#define MCHUNK 4
#define NCHUNK 4
#define TDIM 1024
#define PTILE 32
#define CHW  (CC * HWP)
#define MCHW (MMAPS * CHW)

// attn smem (floats):
//   ysm   [0, 9216)          ysm[c*36 + l]  (float4-aligned)
//   score phase:
//     qk    [9216, 9472)
//     spart [9472, 13696)    2 buffers x (4 m x 16 w x 33)
//   gemm phase (aliases qk/spart):
//     Wvs   [9216, 18432)    Wvs[o*36 + cl], cl<32 used
#define SMEM_FLOATS 18432
#define SMEM_BYTES  (SMEM_FLOATS * 4)

__device__ float g_q [2 * CC];
__device__ float g_qk[2 * CC];

// ---------------- packed f32x2 helpers ----------------
__device__ __forceinline__ unsigned long long pk2(float x, float y) {
    unsigned long long r;
    asm("mov.b64 %0, {%1, %2};" : "=l"(r) : "f"(x), "f"(y));
    return r;
}
__device__ __forceinline__ void upk2(unsigned long long v, float& x, float& y) {
    asm("mov.b64 {%0, %1}, %2;" : "=f"(x), "=f"(y) : "l"(v));
}
__device__ __forceinline__ void fma2(unsigned long long& acc,
                                     unsigned long long a, unsigned long long b) {
    asm("fma.rn.f32x2 %0, %1, %2, %0;" : "+l"(acc) : "l"(a), "l"(b));
}

// ---------------- kernel A: q[b,c] = Wq[c,:]·t[b,:] + bq[c] ----------------
// one warp per (b,c): 512 warps = 64 CTAs x 8 warps; float4 loads (MLP 16)
__global__ void q_proj(const float* __restrict__ to, const float* __restrict__ Wq,
                       const float* __restrict__ bq) {
    const int tid = threadIdx.x, w = tid >> 5, l = tid & 31;
    const int gw = blockIdx.x * 8 + w;          // 0..511
    const int b = gw >> 8, c = gw & 255;
    const float4* wr = (const float4*)(Wq + c * TDIM);
    const float4* tr = (const float4*)(to + b * TDIM);
    float a = 0.f;
    #pragma unroll
    for (int i = 0; i < 8; i++) {
        const float4 wv = __ldg(wr + l + 32 * i);
        const float4 tv = __ldg(tr + l + 32 * i);
        a = fmaf(wv.x, tv.x, a); a = fmaf(wv.y, tv.y, a);
        a = fmaf(wv.z, tv.z, a); a = fmaf(wv.w, tv.w, a);
    }
    #pragma unroll
    for (int off = 16; off > 0; off >>= 1) a += __shfl_down_sync(0xffffffffu, a, off);
    if (l == 0) g_q[b * CC + c] = a + __ldg(bq + c);
}

// ---------------- kernel B: qk[b,cp] = scale * sum_c q[b,c] Wk[c,cp] ----------------
__global__ void qk_proj(const float* __restrict__ Wk) {
    __shared__ float qs[CC];
    __shared__ float part[8][33];
    const int tid = threadIdx.x;
    const int b = blockIdx.x >> 3;
    const int cp0 = (blockIdx.x & 7) * 32;
    if (tid < CC) qs[tid] = g_q[b * CC + tid];
    __syncthreads();
    const int cs = tid >> 5, cp = tid & 31;
    float a = 0.f;
    #pragma unroll 8
    for (int c = cs * 32; c < cs * 32 + 32; c++)
        a = fmaf(qs[c], __ldg(Wk + c * CC + cp0 + cp), a);
    part[cs][cp] = a;
    __syncthreads();
    if (tid < 32) {
        float s = 0.f;
        #pragma unroll
        for (int i = 0; i < 8; i++) s += part[i][tid];
        g_qk[b * CC + cp0 + tid] = s * 0.0625f;   // * C^-0.5
    }
}

// ---------------- kernel C: chunked scores+softmax+weighted-sum, then Wv GEMM ----------------
__global__ void __launch_bounds__(BDIM, 2)
attn_kernel(const float* __restrict__ res, const float* __restrict__ Wv,
            const float* __restrict__ bv, float* __restrict__ out) {
    extern __shared__ float sm[];
    float* ysm   = sm;              // 256 x 36
    float* qk    = sm + 9216;       // 256
    float* spart = sm + 9472;       // 2 x (4 x 16 x 33)
    float* Wvs   = sm + 9216;       // 256 x 36 (gemm phase, aliases qk/spart)

    const int tid = threadIdx.x, w = tid >> 5, l = tid & 31;
    const int b  = blockIdx.x >> 7;
    const int p0 = (blockIdx.x & 127) * PTILE;

    if (tid < CC) qk[tid] = g_qk[b * CC + tid];
    __syncthreads();

    // thread: pixel p0+l, channels c = w + 16k (k = 0..15)
    const float* xb0 = res + (size_t)b * MCHW + (size_t)w * HWP + p0 + l;

    float y[16];
    #pragma unroll
    for (int k = 0; k < 16; k++) y[k] = 0.f;
    float mrun = -1e30f, lrun = 0.f;

    for (int mc = 0; mc < NCHUNK; mc++) {
        const float* xmc = xb0 + (size_t)mc * MCHUNK * CHW;
        const int bufo = (mc & 1) * 2112;

        // pass 1: partial scores for 4 maps (DRAM read; high MLP)
        float sp[MCHUNK];
        #pragma unroll
        for (int j = 0; j < MCHUNK; j++) sp[j] = 0.f;
        #pragma unroll
        for (int k = 0; k < 16; k++) {
            const float qv = qk[w + 16 * k];
            const float* xk = xmc + (size_t)k * NWARP * HWP;
            #pragma unroll
            for (int j = 0; j < MCHUNK; j++)
                sp[j] = fmaf(__ldg(xk + (size_t)j * CHW), qv, sp[j]);
        }
        #pragma unroll
        for (int j = 0; j < MCHUNK; j++) spart[bufo + j * 528 + w * 33 + l] = sp[j];
        __syncthreads();

        // reduce over 16 warps (every thread computes its pixel's 4 scores)
        float st[MCHUNK];
        #pragma unroll
        for (int j = 0; j < MCHUNK; j++) {
            float s = 0.f;
            #pragma unroll
            for (int ww = 0; ww < NWARP; ww++) s += spart[bufo + j * 528 + ww * 33 + l];
            st[j] = s;
        }

        // online softmax update (chunk granularity)
        float mnew = mrun;
        #pragma unroll
        for (int j = 0; j < MCHUNK; j++) mnew = fmaxf(mnew, st[j]);
        const float alpha = __expf(mrun - mnew);
        float f[MCHUNK], fs = 0.f;
        #pragma unroll
        for (int j = 0; j < MCHUNK; j++) { f[j] = __expf(st[j] - mnew); fs += f[j]; }
        lrun = lrun * alpha + fs;
        mrun = mnew;

        // pass 2: weighted accumulate (same 128KB tile, immediately -> L2 hit)
        #pragma unroll
        for (int k = 0; k < 16; k++) y[k] *= alpha;
        #pragma unroll
        for (int j = 0; j < MCHUNK; j++) {
            const float fj = f[j];
            const float* xj = xmc + (size_t)j * CHW;
            #pragma unroll
            for (int k = 0; k < 16; k++)
                y[k] = fmaf(__ldg(xj + (size_t)k * NWARP * HWP), fj, y[k]);
        }
        // single barrier per chunk; spart double-buffered
    }

    const float inv = 1.0f / lrun;
    #pragma unroll
    for (int k = 0; k < 16; k++) ysm[(w + 16 * k) * 36 + l] = y[k] * inv;
    __syncthreads();

    // ---- GEMM: out[o,p] = sum_c Wv[o,c] * ysm[c,p] + bv[o] ----
    // thread -> (og = tid>>3 : 4 o's, pg = tid&7 : 4 p's); c chunked by 32
    const int og = tid >> 3, pg = tid & 7;
    unsigned long long acc[4][2];
    #pragma unroll
    for (int i = 0; i < 4; i++) { acc[i][0] = 0ull; acc[i][1] = 0ull; }

    const float4* ysm4 = (const float4*)ysm;    // row stride 9 float4s

    for (int ch = 0; ch < 8; ch++) {
        // stage Wv[:, ch*32 .. ch*32+31] -> Wvs[o*36 + cl]
        #pragma unroll
        for (int it = 0; it < 4; it++) {
            const int idx = tid + it * BDIM;     // 0..2047 float4s
            const int o = idx >> 3, c4 = idx & 7;
            const float4 v = __ldg((const float4*)(Wv + o * CC + ch * 32 + c4 * 4));
            *(float4*)(Wvs + o * 36 + c4 * 4) = v;
        }
        __syncthreads();

        #pragma unroll
        for (int cl2 = 0; cl2 < 16; cl2++) {
            const int cl = cl2 * 2;
            const int c = ch * 32 + cl;
            const float4 yv0 = ysm4[c * 9 + pg];
            const float4 yv1 = ysm4[(c + 1) * 9 + pg];
            const unsigned long long ya0 = pk2(yv0.x, yv0.y), yb0 = pk2(yv0.z, yv0.w);
            const unsigned long long ya1 = pk2(yv1.x, yv1.y), yb1 = pk2(yv1.z, yv1.w);
            #pragma unroll
            for (int i = 0; i < 4; i++) {
                const float2 wv = *(const float2*)(Wvs + (og * 4 + i) * 36 + cl);
                const unsigned long long w0 = pk2(wv.x, wv.x);
                const unsigned long long w1 = pk2(wv.y, wv.y);
                fma2(acc[i][0], w0, ya0);
                fma2(acc[i][1], w0, yb0);
                fma2(acc[i][0], w1, ya1);
                fma2(acc[i][1], w1, yb1);
            }
        }
        __syncthreads();
    }

    #pragma unroll
    for (int i = 0; i < 4; i++) {
        const int o = og * 4 + i;
        const float bvo = __ldg(bv + o);
        float x0, x1, x2, x3;
        upk2(acc[i][0], x0, x1);
        upk2(acc[i][1], x2, x3);
        float4 ov = make_float4(x0 + bvo, x1 + bvo, x2 + bvo, x3 + bvo);
        *(float4*)(out + ((size_t)b * CC + o) * HWP + p0 + pg * 4) = ov;
    }
}

extern "C" void kernel_launch(void* const* d_in, const int* in_sizes, int n_in,
                              void* d_out, int out_size) {
    const float* to  = (const float*)d_in[0];  // [B, T]
    const float* res = (const float*)d_in[1];  // [B, M, C, H, W]
    const float* Wq  = (const float*)d_in[2];  // [C, T]
    const float* bq  = (const float*)d_in[3];  // [C]
    const float* Wk  = (const float*)d_in[4];  // [C, C]
    // d_in[5] = bk : cancels in softmax
    const float* Wv  = (const float*)d_in[6];  // [C, C]
    const float* bv  = (const float*)d_in[7];  // [C]
    float* out = (float*)d_out;                // [B, C, H, W]

    cudaFuncSetAttribute(attn_kernel, cudaFuncAttributeMaxDynamicSharedMemorySize,
                         SMEM_BYTES);

    q_proj<<<64, 256>>>(to, Wq, bq);
    qk_proj<<<16, 256>>>(Wk);
    attn_kernel<<<256, BDIM, SMEM_BYTES>>>(res, Wv, bv, out);
}

// round 13
// speedup vs baseline: 1.4252x; 1.4252x over previous
#include <cuda_runtime.h>

// TemporalAttention: B=2, M=16, C=256, H=W=64 (HW=4096), T=1024
// out[b,o,p] = sum_c Wv[o,c] * ( sum_m softmax_m(scale * qk[b]·x[b,m,:,p]) * x[b,m,c,p] ) + bv[o]
// qk[b] = scale * Wk^T (Wq t[b] + bq); bk cancels in softmax; bv hoists (sum_m p_m = 1).

#define BDIM 512
#define CC   256
#define HWP  4096
#define MMAPS 16
#define TDIM 1024
#define PTILE 32
#define CHW  (CC * HWP)
#define MCHW (MMAPS * CHW)

// attn smem (floats):
//  streaming phase:
//   buf0 [0, 8448)        x tile, xs[c*33 + px]
//   buf1 [8448, 16896)
//   qk   [16896, 17152)
//   sc   [17152, 17184)
//  gemm phase (aliases everything):
//   ysm  [0, 9216)        ysm[c*36 + px]
//   Wvs  [9216, 18432)    Wvs[o*36 + cl]
#define BUFF 8448
#define SMEM_FLOATS 18432
#define SMEM_BYTES  (SMEM_FLOATS * 4)

__device__ float g_q [2 * CC];
__device__ float g_qk[2 * CC];

// ---------------- packed f32x2 helpers ----------------
__device__ __forceinline__ unsigned long long pk2(float x, float y) {
    unsigned long long r;
    asm("mov.b64 %0, {%1, %2};" : "=l"(r) : "f"(x), "f"(y));
    return r;
}
__device__ __forceinline__ void upk2(unsigned long long v, float& x, float& y) {
    asm("mov.b64 {%0, %1}, %2;" : "=f"(x), "=f"(y) : "l"(v));
}
__device__ __forceinline__ void fma2(unsigned long long& acc,
                                     unsigned long long a, unsigned long long b) {
    asm("fma.rn.f32x2 %0, %1, %2, %0;" : "+l"(acc) : "l"(a), "l"(b));
}
__device__ __forceinline__ void cp4(unsigned dst, const float* src) {
    asm volatile("cp.async.ca.shared.global [%0], [%1], 4;" :: "r"(dst), "l"(src) : "memory");
}
__device__ __forceinline__ void cp_commit() {
    asm volatile("cp.async.commit_group;" ::: "memory");
}
__device__ __forceinline__ void cp_wait1() {
    asm volatile("cp.async.wait_group 1;" ::: "memory");
}
__device__ __forceinline__ void cp_wait0() {
    asm volatile("cp.async.wait_group 0;" ::: "memory");
}

// ---------------- kernel A: q[b,c] = Wq[c,:]·t[b,:] + bq[c] ----------------
// one warp per c, both b's (Wq row read once): 256 warps = 64 CTAs x 4 warps
__global__ void q_proj(const float* __restrict__ to, const float* __restrict__ Wq,
                       const float* __restrict__ bq) {
    const int tid = threadIdx.x, w = tid >> 5, l = tid & 31;
    const int c = blockIdx.x * 4 + w;           // 0..255
    const float4* wr = (const float4*)(Wq + c * TDIM);
    const float4* t0 = (const float4*)(to);
    const float4* t1 = (const float4*)(to + TDIM);
    float a0 = 0.f, a1 = 0.f;
    #pragma unroll
    for (int i = 0; i < 8; i++) {
        const float4 wv = __ldg(wr + l + 32 * i);
        const float4 u0 = __ldg(t0 + l + 32 * i);
        const float4 u1 = __ldg(t1 + l + 32 * i);
        a0 = fmaf(wv.x, u0.x, a0); a0 = fmaf(wv.y, u0.y, a0);
        a0 = fmaf(wv.z, u0.z, a0); a0 = fmaf(wv.w, u0.w, a0);
        a1 = fmaf(wv.x, u1.x, a1); a1 = fmaf(wv.y, u1.y, a1);
        a1 = fmaf(wv.z, u1.z, a1); a1 = fmaf(wv.w, u1.w, a1);
    }
    #pragma unroll
    for (int off = 16; off > 0; off >>= 1) {
        a0 += __shfl_down_sync(0xffffffffu, a0, off);
        a1 += __shfl_down_sync(0xffffffffu, a1, off);
    }
    if (l == 0) {
        const float bqc = __ldg(bq + c);
        g_q[c]      = a0 + bqc;
        g_q[CC + c] = a1 + bqc;
    }
}

// ---------------- kernel B: qk[b,cp] = scale * sum_c q[b,c] Wk[c,cp] ----------------
__global__ void qk_proj(const float* __restrict__ Wk) {
    __shared__ float qs[CC];
    __shared__ float part[8][33];
    const int tid = threadIdx.x;
    const int b = blockIdx.x >> 3;
    const int cp0 = (blockIdx.x & 7) * 32;
    if (tid < CC) qs[tid] = g_q[b * CC + tid];
    __syncthreads();
    const int cs = tid >> 5, cp = tid & 31;
    float a = 0.f;
    #pragma unroll 8
    for (int c = cs * 32; c < cs * 32 + 32; c++)
        a = fmaf(qs[c], __ldg(Wk + c * CC + cp0 + cp), a);
    part[cs][cp] = a;
    __syncthreads();
    if (tid < 32) {
        float s = 0.f;
        #pragma unroll
        for (int i = 0; i < 8; i++) s += part[i][tid];
        g_qk[b * CC + cp0 + tid] = s * 0.0625f;   // * C^-0.5
    }
}

// ---------------- kernel C: cp.async-pipelined single-pass attn + Wv GEMM ----------------
__global__ void __launch_bounds__(BDIM, 2)
attn_kernel(const float* __restrict__ res, const float* __restrict__ Wv,
            const float* __restrict__ bv, float* __restrict__ out) {
    extern __shared__ float sm[];
    float* qk  = sm + 2 * BUFF;         // 256
    float* sc  = sm + 2 * BUFF + 256;   // 32
    float* ysm = sm;                    // gemm: 256 x 36
    float* Wvs = sm + 9216;             // gemm: 256 x 36

    const int tid = threadIdx.x, w = tid >> 5, l = tid & 31;
    const int b  = blockIdx.x >> 7;
    const int p0 = (blockIdx.x & 127) * PTILE;

    const unsigned smem_u32 = (unsigned)__cvta_generic_to_shared(sm);
    const float* src0 = res + (size_t)b * MCHW + p0;

    if (tid < CC) qk[tid] = g_qk[b * CC + tid];

    // prologue: issue tile 0 into buf0
    {
        const float* src = src0;
        #pragma unroll
        for (int j = 0; j < 16; j++) {
            const int idx = tid + j * BDIM;          // 0..8191
            const int c = idx >> 5, px = idx & 31;
            cp4(smem_u32 + (unsigned)(c * 33 + px) * 4u, src + (size_t)c * HWP + px);
        }
        cp_commit();
    }

    float y[16];
    #pragma unroll
    for (int k = 0; k < 16; k++) y[k] = 0.f;
    float mrun = -1e30f, lrun = 0.f;
    const int px0 = w * 2, px1 = w * 2 + 1;

    for (int m = 0; m < MMAPS; m++) {
        // issue tile m+1 into the other buffer (readers of it finished at prior T3)
        if (m + 1 < MMAPS) {
            const float* src = src0 + (size_t)(m + 1) * CHW;
            const unsigned dstb = smem_u32 + (unsigned)(((m + 1) & 1) * BUFF) * 4u;
            #pragma unroll
            for (int j = 0; j < 16; j++) {
                const int idx = tid + j * BDIM;
                const int c = idx >> 5, px = idx & 31;
                cp4(dstb + (unsigned)(c * 33 + px) * 4u, src + (size_t)c * HWP + px);
            }
            cp_commit();
            cp_wait1();                 // tile m complete (m+1 still in flight)
        } else {
            cp_wait0();
        }
        __syncthreads();                // T1: tile m visible to all

        const float* xs = sm + (m & 1) * BUFF;

        // score: warp-local, 2 pixels per warp, lanes split c
        float s0 = 0.f, s1 = 0.f;
        #pragma unroll
        for (int j = 0; j < 8; j++) {
            const int c = l + 32 * j;
            const float qv = qk[c];
            s0 = fmaf(qv, xs[c * 33 + px0], s0);
            s1 = fmaf(qv, xs[c * 33 + px1], s1);
        }
        #pragma unroll
        for (int off = 16; off > 0; off >>= 1) {
            s0 += __shfl_xor_sync(0xffffffffu, s0, off);
            s1 += __shfl_xor_sync(0xffffffffu, s1, off);
        }
        if (l == 0) { sc[px0] = s0; sc[px1] = s1; }
        __syncthreads();                // T2: sc visible

        // online softmax + y accumulate (thread: pixel l, channels w+16k)
        const float st = sc[l];
        const float mnew  = fmaxf(mrun, st);
        const float alpha = __expf(mrun - mnew);
        const float f     = __expf(st - mnew);
        lrun = lrun * alpha + f;
        mrun = mnew;
        #pragma unroll
        for (int k = 0; k < 16; k++)
            y[k] = fmaf(xs[(w + 16 * k) * 33 + l], f, y[k] * alpha);
        __syncthreads();                // T3: buffer reads done -> safe to refill
    }

    // stage normalized y into ysm (stride 36, float4-aligned rows)
    const float inv = 1.0f / lrun;
    #pragma unroll
    for (int k = 0; k < 16; k++) ysm[(w + 16 * k) * 36 + l] = y[k] * inv;
    __syncthreads();

    // ---- GEMM: out[o,p] = sum_c Wv[o,c] * ysm[c,p] + bv[o] ----
    const int og = tid >> 3, pg = tid & 7;
    unsigned long long acc[4][2];
    #pragma unroll
    for (int i = 0; i < 4; i++) { acc[i][0] = 0ull; acc[i][1] = 0ull; }

    const float4* ysm4 = (const float4*)ysm;    // row stride 9 float4s

    for (int ch = 0; ch < 8; ch++) {
        #pragma unroll
        for (int it = 0; it < 4; it++) {
            const int idx = tid + it * BDIM;     // 0..2047 float4s
            const int o = idx >> 3, c4 = idx & 7;
            const float4 v = __ldg((const float4*)(Wv + o * CC + ch * 32 + c4 * 4));
            *(float4*)(Wvs + o * 36 + c4 * 4) = v;
        }
        __syncthreads();

        #pragma unroll
        for (int cl2 = 0; cl2 < 16; cl2++) {
            const int cl = cl2 * 2;
            const int c = ch * 32 + cl;
            const float4 yv0 = ysm4[c * 9 + pg];
            const float4 yv1 = ysm4[(c + 1) * 9 + pg];
            const unsigned long long ya0 = pk2(yv0.x, yv0.y), yb0 = pk2(yv0.z, yv0.w);
            const unsigned long long ya1 = pk2(yv1.x, yv1.y), yb1 = pk2(yv1.z, yv1.w);
            #pragma unroll
            for (int i = 0; i < 4; i++) {
                const float2 wv = *(const float2*)(Wvs + (og * 4 + i) * 36 + cl);
                const unsigned long long w0 = pk2(wv.x, wv.x);
                const unsigned long long w1 = pk2(wv.y, wv.y);
                fma2(acc[i][0], w0, ya0);
                fma2(acc[i][1], w0, yb0);
                fma2(acc[i][0], w1, ya1);
                fma2(acc[i][1], w1, yb1);
            }
        }
        __syncthreads();
    }

    #pragma unroll
    for (int i = 0; i < 4; i++) {
        const int o = og * 4 + i;
        const float bvo = __ldg(bv + o);
        float x0, x1, x2, x3;
        upk2(acc[i][0], x0, x1);
        upk2(acc[i][1], x2, x3);
        float4 ov = make_float4(x0 + bvo, x1 + bvo, x2 + bvo, x3 + bvo);
        *(float4*)(out + ((size_t)b * CC + o) * HWP + p0 + pg * 4) = ov;
    }
}

extern "C" void kernel_launch(void* const* d_in, const int* in_sizes, int n_in,
                              void* d_out, int out_size) {
    const float* to  = (const float*)d_in[0];  // [B, T]
    const float* res = (const float*)d_in[1];  // [B, M, C, H, W]
    const float* Wq  = (const float*)d_in[2];  // [C, T]
    const float* bq  = (const float*)d_in[3];  // [C]
    const float* Wk  = (const float*)d_in[4];  // [C, C]
    // d_in[5] = bk : cancels in softmax
    const float* Wv  = (const float*)d_in[6];  // [C, C]
    const float* bv  = (const float*)d_in[7];  // [C]
    float* out = (float*)d_out;                // [B, C, H, W]

    cudaFuncSetAttribute(attn_kernel, cudaFuncAttributeMaxDynamicSharedMemorySize,
                         SMEM_BYTES);

    q_proj<<<64, 128>>>(to, Wq, bq);
    qk_proj<<<16, 256>>>(Wk);
    attn_kernel<<<256, BDIM, SMEM_BYTES>>>(res, Wv, bv, out);
}

// round 14
// speedup vs baseline: 1.4495x; 1.0170x over previous
#include <cuda_runtime.h>

// TemporalAttention: B=2, M=16, C=256, H=W=64 (HW=4096), T=1024
// out[b,o,p] = sum_c Wv[o,c] * ( sum_m softmax_m(scale * qk[b]·x[b,m,:,p]) * x[b,m,c,p] ) + bv[o]
// qk[b] = scale * Wk^T (Wq t[b] + bq); bk cancels in softmax; bv hoists (sum_m p_m = 1).

#define BDIM 512
#define CC   256
#define HWP  4096
#define MMAPS 16
#define TDIM 1024
#define PTILE 32
#define CHW  (CC * HWP)
#define MCHW (MMAPS * CHW)

// attn smem (floats):
//  streaming phase:
//   buf[3]  [0, 25344)       x tiles, xs[c*33 + px], 8448 floats each
//   qk      [25344, 25600)
//  gemm phase (aliases buffers):
//   ysm  [0, 9216)           ysm[c*36 + px]
//   Wvs  [9216, 18432)       Wvs[o*36 + cl]
#define BUFF 8448
#define SMEM_FLOATS 25600
#define SMEM_BYTES  (SMEM_FLOATS * 4)

__device__ float g_q [2 * CC];
__device__ float g_qk[2 * CC];

// ---------------- packed f32x2 helpers ----------------
__device__ __forceinline__ unsigned long long pk2(float x, float y) {
    unsigned long long r;
    asm("mov.b64 %0, {%1, %2};" : "=l"(r) : "f"(x), "f"(y));
    return r;
}
__device__ __forceinline__ void upk2(unsigned long long v, float& x, float& y) {
    asm("mov.b64 {%0, %1}, %2;" : "=f"(x), "=f"(y) : "l"(v));
}
__device__ __forceinline__ void fma2(unsigned long long& acc,
                                     unsigned long long a, unsigned long long b) {
    asm("fma.rn.f32x2 %0, %1, %2, %0;" : "+l"(acc) : "l"(a), "l"(b));
}
__device__ __forceinline__ void cp4(unsigned dst, const float* src) {
    asm volatile("cp.async.ca.shared.global [%0], [%1], 4;" :: "r"(dst), "l"(src) : "memory");
}
__device__ __forceinline__ void cp_commit() {
    asm volatile("cp.async.commit_group;" ::: "memory");
}
__device__ __forceinline__ void cp_wait1() {
    asm volatile("cp.async.wait_group 1;" ::: "memory");
}
__device__ __forceinline__ void cp_wait0() {
    asm volatile("cp.async.wait_group 0;" ::: "memory");
}

// ---------------- kernel A: q[b,c] = Wq[c,:]·t[b,:] + bq[c] ----------------
// one CTA per c (256 CTAs x 128 threads), both b's share the Wq row read.
__global__ void q_proj(const float* __restrict__ to, const float* __restrict__ Wq,
                       const float* __restrict__ bq) {
    __shared__ float red[8];                    // [b][warp]
    const int c = blockIdx.x;
    const int tid = threadIdx.x, w = tid >> 5, l = tid & 31;
    const float4* wr = (const float4*)(Wq + c * TDIM);
    const float4* t0 = (const float4*)(to);
    const float4* t1 = (const float4*)(to + TDIM);
    float a0 = 0.f, a1 = 0.f;
    #pragma unroll
    for (int i = 0; i < 2; i++) {
        const int idx = tid + i * 128;          // 0..255 float4s
        const float4 wv = __ldg(wr + idx);
        const float4 u0 = __ldg(t0 + idx);
        const float4 u1 = __ldg(t1 + idx);
        a0 = fmaf(wv.x, u0.x, a0); a0 = fmaf(wv.y, u0.y, a0);
        a0 = fmaf(wv.z, u0.z, a0); a0 = fmaf(wv.w, u0.w, a0);
        a1 = fmaf(wv.x, u1.x, a1); a1 = fmaf(wv.y, u1.y, a1);
        a1 = fmaf(wv.z, u1.z, a1); a1 = fmaf(wv.w, u1.w, a1);
    }
    #pragma unroll
    for (int off = 16; off > 0; off >>= 1) {
        a0 += __shfl_down_sync(0xffffffffu, a0, off);
        a1 += __shfl_down_sync(0xffffffffu, a1, off);
    }
    if (l == 0) { red[w] = a0; red[4 + w] = a1; }
    __syncthreads();
    if (tid < 2) {
        const float bqc = __ldg(bq + c);
        float s = red[tid * 4] + red[tid * 4 + 1] + red[tid * 4 + 2] + red[tid * 4 + 3];
        g_q[tid * CC + c] = s + bqc;
    }
}

// ---------------- kernel B: qk[b,cp] = scale * sum_c q[b,c] Wk[c,cp] ----------------
// grid 32: b = blk>>4, 16-wide cp chunk; 256 threads = 16 c-slices x 16 cp.
__global__ void qk_proj(const float* __restrict__ Wk) {
    __shared__ float qs[CC];
    __shared__ float part[16][17];
    const int tid = threadIdx.x;
    const int b = blockIdx.x >> 4;
    const int cp0 = (blockIdx.x & 15) * 16;
    qs[tid] = g_q[b * CC + tid];
    __syncthreads();
    const int cs = tid >> 4, cp = tid & 15;
    float a = 0.f;
    #pragma unroll
    for (int c = cs * 16; c < cs * 16 + 16; c++)
        a = fmaf(qs[c], __ldg(Wk + c * CC + cp0 + cp), a);
    part[cs][cp] = a;
    __syncthreads();
    if (tid < 16) {
        float s = 0.f;
        #pragma unroll
        for (int i = 0; i < 16; i++) s += part[i][tid];
        g_qk[b * CC + cp0 + tid] = s * 0.0625f;   // * C^-0.5
    }
}

// ---------------- kernel C: warp-autonomous single-pass attn + Wv GEMM ----------------
__global__ void __launch_bounds__(BDIM, 2)
attn_kernel(const float* __restrict__ res, const float* __restrict__ Wv,
            const float* __restrict__ bv, float* __restrict__ out) {
    extern __shared__ float sm[];
    float* qk  = sm + 3 * BUFF;         // 256
    float* ysm = sm;                    // gemm: 256 x 36
    float* Wvs = sm + 9216;             // gemm: 256 x 36

    const int tid = threadIdx.x, w = tid >> 5, l = tid & 31;
    const int b  = blockIdx.x >> 7;
    const int p0 = (blockIdx.x & 127) * PTILE;

    const unsigned smem_u32 = (unsigned)__cvta_generic_to_shared(sm);
    const float* src0 = res + (size_t)b * MCHW + p0;

    if (tid < CC) qk[tid] = g_qk[b * CC + tid];

    // prologue: issue tiles 0 and 1
    #pragma unroll
    for (int t = 0; t < 2; t++) {
        const float* src = src0 + (size_t)t * CHW;
        const unsigned dstb = smem_u32 + (unsigned)(t * BUFF) * 4u;
        #pragma unroll
        for (int j = 0; j < 16; j++) {
            const int idx = tid + j * BDIM;          // 0..8191
            const int c = idx >> 5, px = idx & 31;
            cp4(dstb + (unsigned)(c * 33 + px) * 4u, src + (size_t)c * HWP + px);
        }
        cp_commit();
    }

    // warp owns pixels px0 = 2w, px1 = 2w+1; lane owns channels c = l + 32k
    const int px0 = w * 2, px1 = px0 + 1;
    float y0[8], y1[8];
    #pragma unroll
    for (int k = 0; k < 8; k++) { y0[k] = 0.f; y1[k] = 0.f; }
    float m0 = -1e30f, l0 = 0.f, m1 = -1e30f, l1 = 0.f;

    for (int m = 0; m < MMAPS; m++) {
        if (m < MMAPS - 1) cp_wait1(); else cp_wait0();   // tile m arrived
        __syncthreads();   // publish tile m; close reads of buf[(m+2)%3] (tile m-1)

        // issue tile m+2 into the just-freed buffer
        if (m + 2 < MMAPS) {
            const float* src = src0 + (size_t)(m + 2) * CHW;
            const unsigned dstb = smem_u32 + (unsigned)(((m + 2) % 3) * BUFF) * 4u;
            #pragma unroll
            for (int j = 0; j < 16; j++) {
                const int idx = tid + j * BDIM;
                const int c = idx >> 5, px = idx & 31;
                cp4(dstb + (unsigned)(c * 33 + px) * 4u, src + (size_t)c * HWP + px);
            }
            cp_commit();
        }

        const float* xs = sm + (m % 3) * BUFF;

        // score + keep x values in regs for the y update
        float xv0[8], xv1[8];
        float s0 = 0.f, s1 = 0.f;
        #pragma unroll
        for (int k = 0; k < 8; k++) {
            const int c = l + 32 * k;
            const float qv = qk[c];
            xv0[k] = xs[c * 33 + px0];
            xv1[k] = xs[c * 33 + px1];
            s0 = fmaf(qv, xv0[k], s0);
            s1 = fmaf(qv, xv1[k], s1);
        }
        #pragma unroll
        for (int off = 16; off > 0; off >>= 1) {
            s0 += __shfl_xor_sync(0xffffffffu, s0, off);
            s1 += __shfl_xor_sync(0xffffffffu, s1, off);
        }

        // per-pixel online softmax (warp-uniform; no smem, no barrier)
        const float n0 = fmaxf(m0, s0);
        const float a0 = __expf(m0 - n0);
        const float f0 = __expf(s0 - n0);
        l0 = l0 * a0 + f0; m0 = n0;
        const float n1 = fmaxf(m1, s1);
        const float a1 = __expf(m1 - n1);
        const float f1 = __expf(s1 - n1);
        l1 = l1 * a1 + f1; m1 = n1;

        #pragma unroll
        for (int k = 0; k < 8; k++) {
            y0[k] = fmaf(xv0[k], f0, y0[k] * a0);
            y1[k] = fmaf(xv1[k], f1, y1[k] * a1);
        }
    }

    __syncthreads();   // all tile reads done before ysm overwrites buffers

    const float i0 = 1.0f / l0, i1 = 1.0f / l1;
    #pragma unroll
    for (int k = 0; k < 8; k++) {
        const int c = l + 32 * k;
        ysm[c * 36 + px0] = y0[k] * i0;
        ysm[c * 36 + px1] = y1[k] * i1;
    }
    __syncthreads();

    // ---- GEMM: out[o,p] = sum_c Wv[o,c] * ysm[c,p] + bv[o] ----
    const int og = tid >> 3, pg = tid & 7;
    unsigned long long acc[4][2];
    #pragma unroll
    for (int i = 0; i < 4; i++) { acc[i][0] = 0ull; acc[i][1] = 0ull; }

    const float4* ysm4 = (const float4*)ysm;    // row stride 9 float4s

    for (int ch = 0; ch < 8; ch++) {
        #pragma unroll
        for (int it = 0; it < 4; it++) {
            const int idx = tid + it * BDIM;     // 0..2047 float4s
            const int o = idx >> 3, c4 = idx & 7;
            const float4 v = __ldg((const float4*)(Wv + o * CC + ch * 32 + c4 * 4));
            *(float4*)(Wvs + o * 36 + c4 * 4) = v;
        }
        __syncthreads();

        #pragma unroll
        for (int cl2 = 0; cl2 < 16; cl2++) {
            const int cl = cl2 * 2;
            const int c = ch * 32 + cl;
            const float4 yv0 = ysm4[c * 9 + pg];
            const float4 yv1 = ysm4[(c + 1) * 9 + pg];
            const unsigned long long ya0 = pk2(yv0.x, yv0.y), yb0 = pk2(yv0.z, yv0.w);
            const unsigned long long ya1 = pk2(yv1.x, yv1.y), yb1 = pk2(yv1.z, yv1.w);
            #pragma unroll
            for (int i = 0; i < 4; i++) {
                const float2 wv = *(const float2*)(Wvs + (og * 4 + i) * 36 + cl);
                const unsigned long long w0 = pk2(wv.x, wv.x);
                const unsigned long long w1 = pk2(wv.y, wv.y);
                fma2(acc[i][0], w0, ya0);
                fma2(acc[i][1], w0, yb0);
                fma2(acc[i][0], w1, ya1);
                fma2(acc[i][1], w1, yb1);
            }
        }
        __syncthreads();
    }

    #pragma unroll
    for (int i = 0; i < 4; i++) {
        const int o = og * 4 + i;
        const float bvo = __ldg(bv + o);
        float x0, x1, x2, x3;
        upk2(acc[i][0], x0, x1);
        upk2(acc[i][1], x2, x3);
        float4 ov = make_float4(x0 + bvo, x1 + bvo, x2 + bvo, x3 + bvo);
        *(float4*)(out + ((size_t)b * CC + o) * HWP + p0 + pg * 4) = ov;
    }
}

extern "C" void kernel_launch(void* const* d_in, const int* in_sizes, int n_in,
                              void* d_out, int out_size) {
    const float* to  = (const float*)d_in[0];  // [B, T]
    const float* res = (const float*)d_in[1];  // [B, M, C, H, W]
    const float* Wq  = (const float*)d_in[2];  // [C, T]
    const float* bq  = (const float*)d_in[3];  // [C]
    const float* Wk  = (const float*)d_in[4];  // [C, C]
    // d_in[5] = bk : cancels in softmax
    const float* Wv  = (const float*)d_in[6];  // [C, C]
    const float* bv  = (const float*)d_in[7];  // [C]
    float* out = (float*)d_out;                // [B, C, H, W]

    cudaFuncSetAttribute(attn_kernel, cudaFuncAttributeMaxDynamicSharedMemorySize,
                         SMEM_BYTES);

    q_proj<<<256, 128>>>(to, Wq, bq);
    qk_proj<<<32, 256>>>(Wk);
    attn_kernel<<<256, BDIM, SMEM_BYTES>>>(res, Wv, bv, out);
}